// round 6
// baseline (speedup 1.0000x reference)
#include <cuda_runtime.h>
#include <cuda_bf16.h>
#include <cstdint>

#define BATCH 2
#define SEQ 2048
#define HEADS 16
#define DH 64
#define DMODEL 1024
#define MROWS (BATCH*SEQ)   // 4096
#define KDIM 1024
#define NQKV 3072
#define NBH (BATCH*HEADS)   // 32

// ---------------- device scratch (allocation-free rule) ----------------
__device__ __nv_bfloat16 g_Qh[NBH*SEQ*DH];
__device__ __nv_bfloat16 g_Ql[NBH*SEQ*DH];
__device__ __nv_bfloat16 g_Kh[NBH*SEQ*DH];
__device__ __nv_bfloat16 g_Kl[NBH*SEQ*DH];
__device__ float         g_V [NBH*SEQ*DH];
__device__ __nv_bfloat16 g_Vth[NBH*DH*SEQ];   // V^T [bh][d][s]
__device__ __nv_bfloat16 g_Vtl[NBH*DH*SEQ];
__device__ __nv_bfloat16 g_x_hi[MROWS*KDIM];
__device__ __nv_bfloat16 g_x_lo[MROWS*KDIM];
__device__ __nv_bfloat16 g_wq_hi[NQKV*KDIM];   // Wqkv^T [N,K]
__device__ __nv_bfloat16 g_wq_lo[NQKV*KDIM];
__device__ __nv_bfloat16 g_wo_hi[DMODEL*KDIM]; // Wout^T [N,K]
__device__ __nv_bfloat16 g_wo_lo[DMODEL*KDIM];
__device__ __nv_bfloat16 g_attn_hi[MROWS*DMODEL];
__device__ __nv_bfloat16 g_attn_lo[MROWS*DMODEL];

// ---------------- helpers ----------------
__device__ __forceinline__ uint32_t smem_u32(const void* p) {
    uint32_t a;
    asm("{ .reg .u64 t; cvta.to.shared.u64 t, %1; cvt.u32.u64 %0, t; }" : "=r"(a) : "l"(p));
    return a;
}
__device__ __forceinline__ void cpa16(uint32_t dst, const void* src) {
    asm volatile("cp.async.cg.shared.global [%0], [%1], 16;" :: "r"(dst), "l"(src) : "memory");
}
__device__ __forceinline__ void cpa_commit() {
    asm volatile("cp.async.commit_group;" ::: "memory");
}
__device__ __forceinline__ void ldsm_x4(uint32_t* r, uint32_t addr) {
    asm volatile("ldmatrix.sync.aligned.m8n8.x4.shared.b16 {%0,%1,%2,%3}, [%4];"
        : "=r"(r[0]), "=r"(r[1]), "=r"(r[2]), "=r"(r[3]) : "r"(addr));
}
__device__ __forceinline__ void mma_bf16(float* c, const uint32_t* a, const uint32_t* b) {
    asm volatile(
        "mma.sync.aligned.m16n8k16.row.col.f32.bf16.bf16.f32 "
        "{%0,%1,%2,%3}, {%4,%5,%6,%7}, {%8,%9}, {%0,%1,%2,%3};"
        : "+f"(c[0]), "+f"(c[1]), "+f"(c[2]), "+f"(c[3])
        : "r"(a[0]), "r"(a[1]), "r"(a[2]), "r"(a[3]), "r"(b[0]), "r"(b[1]));
}
__device__ __forceinline__ uint32_t pack_bf2(__nv_bfloat16 a, __nv_bfloat16 b) {
    return (uint32_t)__bfloat16_as_ushort(a) | ((uint32_t)__bfloat16_as_ushort(b) << 16);
}
__device__ __forceinline__ void split_bf(float v, __nv_bfloat16& h, __nv_bfloat16& l) {
    h = __float2bfloat16(v);
    l = __float2bfloat16(v - __bfloat162float(h));
}

// ---------------- split-convert kernels ----------------
__global__ __launch_bounds__(256) void conv_split(const float* __restrict__ in,
                                                  __nv_bfloat16* __restrict__ hi,
                                                  __nv_bfloat16* __restrict__ lo) {
    const size_t i = (size_t)blockIdx.x * 256 + threadIdx.x;
    float4 v = ((const float4*)in)[i];
    __nv_bfloat16 h0, h1, h2, h3, l0, l1, l2, l3;
    split_bf(v.x, h0, l0); split_bf(v.y, h1, l1);
    split_bf(v.z, h2, l2); split_bf(v.w, h3, l3);
    ((uint2*)hi)[i] = make_uint2(pack_bf2(h0, h1), pack_bf2(h2, h3));
    ((uint2*)lo)[i] = make_uint2(pack_bf2(l0, l1), pack_bf2(l2, l3));
}

// W[K,N] (row-major) -> Wt_hi/lo[N,K] bf16
__global__ __launch_bounds__(256) void transpose_split(const float* __restrict__ W,
                                                       __nv_bfloat16* __restrict__ th,
                                                       __nv_bfloat16* __restrict__ tl,
                                                       int K, int N) {
    __shared__ float t[32][33];
    const int tx = threadIdx.x, ty = threadIdx.y;
    #pragma unroll
    for (int r = 0; r < 4; r++) {
        int k = blockIdx.y * 32 + ty + r * 8;
        int n = blockIdx.x * 32 + tx;
        t[ty + r * 8][tx] = W[(size_t)k * N + n];
    }
    __syncthreads();
    #pragma unroll
    for (int r = 0; r < 4; r++) {
        int n = blockIdx.x * 32 + ty + r * 8;
        int k = blockIdx.y * 32 + tx;
        float v = t[tx][ty + r * 8];
        __nv_bfloat16 h, l;
        split_bf(v, h, l);
        th[(size_t)n * K + k] = h;
        tl[(size_t)n * K + k] = l;
    }
}

// V [bh][s][d] fp32 -> Vt hi/lo [bh][d][s] bf16
__global__ __launch_bounds__(256) void vtrans_kernel() {
    __shared__ float t[32][33];
    const int tx = threadIdx.x, ty = threadIdx.y;
    const int d0 = blockIdx.x * 32, s0 = blockIdx.y * 32, bh = blockIdx.z;
    #pragma unroll
    for (int r = 0; r < 4; r++) {
        int s = s0 + ty + r * 8;
        t[ty + r * 8][tx] = g_V[((size_t)bh * SEQ + s) * DH + d0 + tx];
    }
    __syncthreads();
    #pragma unroll
    for (int r = 0; r < 4; r++) {
        int d = d0 + ty + r * 8;
        int s = s0 + tx;
        float v = t[tx][ty + r * 8];
        __nv_bfloat16 h, l;
        split_bf(v, h, l);
        g_Vth[((size_t)bh * DH + d) * SEQ + s] = h;
        g_Vtl[((size_t)bh * DH + d) * SEQ + s] = l;
    }
}

// ---------------- mma.sync bf16x3 GEMM: 128x128 CTA tile, 4 warps (64x64 each) ----------------
#define BK 32
#define ROWB 80
#define MATB (128*ROWB)
#define OFF_AH 0
#define OFF_AL MATB
#define OFF_BH (2*MATB)
#define OFF_BL (3*MATB)
#define STAGEB (4*MATB)
#define NCH (KDIM/BK)
#define SMEM_GEMM (2*STAGEB)

template<int EPI>
__global__ __launch_bounds__(128, 2)
void mma_gemm(const __nv_bfloat16* __restrict__ Ah, const __nv_bfloat16* __restrict__ Al,
              const __nv_bfloat16* __restrict__ Bh, const __nv_bfloat16* __restrict__ Bl,
              const float* __restrict__ bias, float* __restrict__ Cout)
{
    extern __shared__ char smem[];
    const uint32_t sb = smem_u32(smem);
    const int tid = threadIdx.x;
    const int lane = tid & 31;
    const int wid = tid >> 5;          // 0..3
    const int rowBase = blockIdx.y * 128;
    const int colBase = blockIdx.x * 128;
    const int mBase = (wid & 1) * 64;  // warp m offset
    const int nBase = (wid >> 1) * 64; // warp n offset

    auto issue = [&](int c, int st) {
        const int k0 = c * BK;
        const uint32_t base = sb + st * STAGEB;
        #pragma unroll
        for (int j = 0; j < 4; j++) {
            const int u = tid + j * 128;
            const int r = u >> 2, q = u & 3;
            const uint32_t so = (uint32_t)(r * ROWB + q * 16);
            const size_t offA = (size_t)(rowBase + r) * KDIM + k0 + q * 8;
            const size_t offB = (size_t)(colBase + r) * KDIM + k0 + q * 8;
            cpa16(base + OFF_AH + so, Ah + offA);
            cpa16(base + OFF_AL + so, Al + offA);
            cpa16(base + OFF_BH + so, Bh + offB);
            cpa16(base + OFF_BL + so, Bl + offB);
        }
        cpa_commit();
    };

    float acc[4][8][4];
    #pragma unroll
    for (int i = 0; i < 4; i++)
        #pragma unroll
        for (int j = 0; j < 8; j++)
            #pragma unroll
            for (int r = 0; r < 4; r++) acc[i][j][r] = 0.f;

    issue(0, 0);
    issue(1, 1);

    const int ja = lane >> 3;
    const int ra = lane & 7;
    const uint32_t aRowCol = (uint32_t)(((ja & 1) * 8 + ra) * ROWB + (ja >> 1) * 16);
    const uint32_t bRowCol = (uint32_t)((((lane >> 4) * 8) + ra) * ROWB + ((lane >> 3) & 1) * 16);

    for (int c = 0; c < NCH; c++) {
        if (c == NCH - 1)
            asm volatile("cp.async.wait_group 0;" ::: "memory");
        else
            asm volatile("cp.async.wait_group 1;" ::: "memory");
        __syncthreads();

        const int st = c & 1;
        const uint32_t base = sb + st * STAGEB;

        #pragma unroll
        for (int kb = 0; kb < 2; kb++) {
            uint32_t ahf[4][4], alf[4][4];
            #pragma unroll
            for (int mf = 0; mf < 4; mf++) {
                const uint32_t off = (uint32_t)((mBase + mf * 16) * ROWB + kb * 32) + aRowCol;
                ldsm_x4(ahf[mf], base + OFF_AH + off);
                ldsm_x4(alf[mf], base + OFF_AL + off);
            }
            #pragma unroll
            for (int nf2 = 0; nf2 < 4; nf2++) {
                const uint32_t off = (uint32_t)((nBase + nf2 * 16) * ROWB + kb * 32) + bRowCol;
                uint32_t th[4], tl[4];
                ldsm_x4(th, base + OFF_BH + off);
                ldsm_x4(tl, base + OFF_BL + off);
                uint32_t bh0[2] = {th[0], th[1]}, bh1[2] = {th[2], th[3]};
                uint32_t bl0[2] = {tl[0], tl[1]}, bl1[2] = {tl[2], tl[3]};
                // term-major issue order: each accumulator's reuse distance = 8 MMAs
                #pragma unroll
                for (int mf = 0; mf < 4; mf++) {               // hi*hi
                    mma_bf16(acc[mf][nf2 * 2],     ahf[mf], bh0);
                    mma_bf16(acc[mf][nf2 * 2 + 1], ahf[mf], bh1);
                }
                #pragma unroll
                for (int mf = 0; mf < 4; mf++) {               // hi*lo
                    mma_bf16(acc[mf][nf2 * 2],     ahf[mf], bl0);
                    mma_bf16(acc[mf][nf2 * 2 + 1], ahf[mf], bl1);
                }
                #pragma unroll
                for (int mf = 0; mf < 4; mf++) {               // lo*hi
                    mma_bf16(acc[mf][nf2 * 2],     alf[mf], bh0);
                    mma_bf16(acc[mf][nf2 * 2 + 1], alf[mf], bh1);
                }
            }
        }
        __syncthreads();
        if (c + 2 < NCH) issue(c + 2, st);
    }

    // epilogue
    #pragma unroll
    for (int mf = 0; mf < 4; mf++) {
        #pragma unroll
        for (int rp = 0; rp < 2; rp++) {
            const int m = rowBase + mBase + mf * 16 + (lane >> 2) + rp * 8;
            const int b = m >> 11;
            const int s_ = m & (SEQ - 1);
            #pragma unroll
            for (int nf = 0; nf < 8; nf++) {
                const int n0 = colBase + nBase + nf * 8 + (lane & 3) * 2;
                const float v0 = acc[mf][nf][rp * 2 + 0] + bias[n0];
                const float v1 = acc[mf][nf][rp * 2 + 1] + bias[n0 + 1];
                if (EPI == 0) {
                    const int h = n0 / 192;
                    const int rr = n0 - h * 192;
                    const size_t bhBase = (size_t)(b * HEADS + h) * SEQ + s_;
                    __nv_bfloat16 h0, h1, l0, l1;
                    split_bf(v0, h0, l0);
                    split_bf(v1, h1, l1);
                    if (rr < 64) {
                        const size_t idx = bhBase * DH + rr;
                        *(uint32_t*)&g_Qh[idx] = pack_bf2(h0, h1);
                        *(uint32_t*)&g_Ql[idx] = pack_bf2(l0, l1);
                    } else if (rr < 128) {
                        const size_t idx = bhBase * DH + (rr - 64);
                        *(uint32_t*)&g_Kh[idx] = pack_bf2(h0, h1);
                        *(uint32_t*)&g_Kl[idx] = pack_bf2(l0, l1);
                    } else {
                        const size_t idx = bhBase * DH + (rr - 128);
                        *(float2*)&g_V[idx] = make_float2(v0, v1);
                    }
                } else {
                    *(float2*)&Cout[(size_t)m * DMODEL + n0] = make_float2(v0, v1);
                }
            }
        }
    }
}

// ---------------- tensor-core flash attention ----------------
#define ROW2 144
#define FQ_BYTES (128*ROW2)
#define FK_BYTES (64*ROW2)
#define FO_QH 0
#define FO_QL FQ_BYTES
#define FO_STAGE (2*FQ_BYTES)
#define FSTAGEB (4*FK_BYTES)
#define SMEM_FLASH (FO_STAGE + 2*FSTAGEB)

__global__ __launch_bounds__(256, 2)
void flash_mma()
{
    extern __shared__ char smem[];
    const uint32_t sb = smem_u32(smem);
    const int tid = threadIdx.x;
    const int lane = tid & 31;
    const int w = tid >> 5;
    const int qt = blockIdx.x;
    const int bh = blockIdx.y;
    const int qb = qt * 128;
    const int nt = 2 * qt + 2;

    const int lr = lane >> 2;
    const int lc = (lane & 3) * 2;

    const __nv_bfloat16* Qh = g_Qh + (size_t)bh * SEQ * DH;
    const __nv_bfloat16* Ql = g_Ql + (size_t)bh * SEQ * DH;
    const __nv_bfloat16* Kh = g_Kh + (size_t)bh * SEQ * DH;
    const __nv_bfloat16* Kl = g_Kl + (size_t)bh * SEQ * DH;
    const __nv_bfloat16* Vth = g_Vth + (size_t)bh * DH * SEQ;
    const __nv_bfloat16* Vtl = g_Vtl + (size_t)bh * DH * SEQ;

    {
        #pragma unroll
        for (int j = 0; j < 4; j++) {
            const int u = tid + j * 256;
            const int r = u >> 3, c = u & 7;
            const uint32_t so = (uint32_t)(r * ROW2 + c * 16);
            const size_t off = (size_t)(qb + r) * DH + c * 8;
            cpa16(sb + FO_QH + so, Qh + off);
            cpa16(sb + FO_QL + so, Ql + off);
        }
    }

    auto issueKV = [&](int t, int st) {
        const int kv0 = t * 64;
        const uint32_t base = sb + FO_STAGE + st * FSTAGEB;
        #pragma unroll
        for (int j = 0; j < 2; j++) {
            const int u = tid + j * 256;
            const int r = u >> 3, c = u & 7;
            const uint32_t so = (uint32_t)(r * ROW2 + c * 16);
            const size_t offK = (size_t)(kv0 + r) * DH + c * 8;
            const size_t offV = (size_t)r * SEQ + kv0 + c * 8;
            cpa16(base + 0 * FK_BYTES + so, Kh + offK);
            cpa16(base + 1 * FK_BYTES + so, Kl + offK);
            cpa16(base + 2 * FK_BYTES + so, Vth + offV);
            cpa16(base + 3 * FK_BYTES + so, Vtl + offV);
        }
        cpa_commit();
    };

    issueKV(0, 0);
    issueKV(1, 1);

    const int ja = lane >> 3;
    const int ra = lane & 7;
    const uint32_t aRowCol = (uint32_t)(((ja & 1) * 8 + ra) * ROW2 + (ja >> 1) * 16);
    const uint32_t bRowCol = (uint32_t)((((lane >> 4) * 8) + ra) * ROW2 + ((lane >> 3) & 1) * 16);
    const uint32_t qWarpOff = (uint32_t)(w * 16) * ROW2 + aRowCol;

    float oacc[8][4];
    #pragma unroll
    for (int nf = 0; nf < 8; nf++)
        #pragma unroll
        for (int r = 0; r < 4; r++) oacc[nf][r] = 0.f;
    float m0 = -1e30f, m1 = -1e30f, l0 = 0.f, l1 = 0.f;

    const int qrow_last = qb + w * 16 + 15;

    for (int t = 0; t < nt; t++) {
        if (t == nt - 1)
            asm volatile("cp.async.wait_group 0;" ::: "memory");
        else
            asm volatile("cp.async.wait_group 1;" ::: "memory");
        __syncthreads();

        const int kv0 = t * 64;
        const int st = t & 1;
        const uint32_t base = sb + FO_STAGE + st * FSTAGEB;

        if (kv0 <= qrow_last) {
            float sacc[8][4];
            #pragma unroll
            for (int nf = 0; nf < 8; nf++)
                #pragma unroll
                for (int r = 0; r < 4; r++) sacc[nf][r] = 0.f;

            #pragma unroll
            for (int kf = 0; kf < 4; kf++) {
                uint32_t qh4[4], ql4[4];
                ldsm_x4(qh4, sb + FO_QH + qWarpOff + kf * 32);
                ldsm_x4(ql4, sb + FO_QL + qWarpOff + kf * 32);
                uint32_t bb[8][2];
                #pragma unroll
                for (int nf2 = 0; nf2 < 4; nf2++) {
                    uint32_t t4[4];
                    ldsm_x4(t4, base + 0 * FK_BYTES +
                            (uint32_t)(nf2 * 16) * ROW2 + kf * 32 + bRowCol);
                    bb[nf2*2][0] = t4[0]; bb[nf2*2][1] = t4[1];
                    bb[nf2*2+1][0] = t4[2]; bb[nf2*2+1][1] = t4[3];
                }
                // term-major: reuse distance 8
                #pragma unroll
                for (int nf = 0; nf < 8; nf++)
                    mma_bf16(sacc[nf], qh4, bb[nf]);   // qh*kh
                #pragma unroll
                for (int nf = 0; nf < 8; nf++)
                    mma_bf16(sacc[nf], ql4, bb[nf]);   // ql*kh
                #pragma unroll
                for (int nf2 = 0; nf2 < 4; nf2++) {
                    uint32_t t4[4];
                    ldsm_x4(t4, base + 1 * FK_BYTES +
                            (uint32_t)(nf2 * 16) * ROW2 + kf * 32 + bRowCol);
                    bb[nf2*2][0] = t4[0]; bb[nf2*2][1] = t4[1];
                    bb[nf2*2+1][0] = t4[2]; bb[nf2*2+1][1] = t4[3];
                }
                #pragma unroll
                for (int nf = 0; nf < 8; nf++)
                    mma_bf16(sacc[nf], qh4, bb[nf]);   // qh*kl
            }

            const bool needMask = (kv0 + 63) > (qb + w * 16);
            const int row0 = qb + w * 16 + lr;
            const int row1 = row0 + 8;
            #pragma unroll
            for (int nf = 0; nf < 8; nf++) {
                const int c0 = kv0 + nf * 8 + lc;
                #pragma unroll
                for (int r = 0; r < 4; r++) {
                    float v = sacc[nf][r] * 0.125f;
                    if (needMask) {
                        const int col = c0 + (r & 1);
                        const int row = (r < 2) ? row0 : row1;
                        if (col > row) v = -1e30f;
                    }
                    sacc[nf][r] = v;
                }
            }

            float mx0 = -1e30f, mx1 = -1e30f;
            #pragma unroll
            for (int nf = 0; nf < 8; nf++) {
                mx0 = fmaxf(mx0, fmaxf(sacc[nf][0], sacc[nf][1]));
                mx1 = fmaxf(mx1, fmaxf(sacc[nf][2], sacc[nf][3]));
            }
            mx0 = fmaxf(mx0, __shfl_xor_sync(0xffffffffu, mx0, 1));
            mx0 = fmaxf(mx0, __shfl_xor_sync(0xffffffffu, mx0, 2));
            mx1 = fmaxf(mx1, __shfl_xor_sync(0xffffffffu, mx1, 1));
            mx1 = fmaxf(mx1, __shfl_xor_sync(0xffffffffu, mx1, 2));
            const float nm0 = fmaxf(m0, mx0);
            const float nm1 = fmaxf(m1, mx1);
            const float corr0 = __expf(m0 - nm0);
            const float corr1 = __expf(m1 - nm1);
            m0 = nm0; m1 = nm1;

            float rs0 = 0.f, rs1 = 0.f;
            #pragma unroll
            for (int nf = 0; nf < 8; nf++) {
                float p0 = __expf(sacc[nf][0] - m0);
                float p1 = __expf(sacc[nf][1] - m0);
                float p2 = __expf(sacc[nf][2] - m1);
                float p3 = __expf(sacc[nf][3] - m1);
                sacc[nf][0] = p0; sacc[nf][1] = p1;
                sacc[nf][2] = p2; sacc[nf][3] = p3;
                rs0 += p0 + p1; rs1 += p2 + p3;
            }
            rs0 += __shfl_xor_sync(0xffffffffu, rs0, 1);
            rs0 += __shfl_xor_sync(0xffffffffu, rs0, 2);
            rs1 += __shfl_xor_sync(0xffffffffu, rs1, 1);
            rs1 += __shfl_xor_sync(0xffffffffu, rs1, 2);
            l0 = l0 * corr0 + rs0;
            l1 = l1 * corr1 + rs1;

            #pragma unroll
            for (int nf = 0; nf < 8; nf++) {
                oacc[nf][0] *= corr0; oacc[nf][1] *= corr0;
                oacc[nf][2] *= corr1; oacc[nf][3] *= corr1;
            }

            #pragma unroll
            for (int kf = 0; kf < 4; kf++) {
                __nv_bfloat16 h0, h1, h2, h3, e0, e1, e2, e3;
                uint32_t ph[4], pl[4];
                split_bf(sacc[2*kf][0], h0, e0); split_bf(sacc[2*kf][1], h1, e1);
                split_bf(sacc[2*kf][2], h2, e2); split_bf(sacc[2*kf][3], h3, e3);
                ph[0] = pack_bf2(h0, h1); ph[1] = pack_bf2(h2, h3);
                pl[0] = pack_bf2(e0, e1); pl[1] = pack_bf2(e2, e3);
                split_bf(sacc[2*kf+1][0], h0, e0); split_bf(sacc[2*kf+1][1], h1, e1);
                split_bf(sacc[2*kf+1][2], h2, e2); split_bf(sacc[2*kf+1][3], h3, e3);
                ph[2] = pack_bf2(h0, h1); ph[3] = pack_bf2(h2, h3);
                pl[2] = pack_bf2(e0, e1); pl[3] = pack_bf2(e2, e3);

                uint32_t bv[8][2];
                #pragma unroll
                for (int nf2 = 0; nf2 < 4; nf2++) {
                    uint32_t t4[4];
                    ldsm_x4(t4, base + 2 * FK_BYTES +
                            (uint32_t)(nf2 * 16) * ROW2 + kf * 32 + bRowCol);
                    bv[nf2*2][0] = t4[0]; bv[nf2*2][1] = t4[1];
                    bv[nf2*2+1][0] = t4[2]; bv[nf2*2+1][1] = t4[3];
                }
                // term-major: distance 8
                #pragma unroll
                for (int nf = 0; nf < 8; nf++)
                    mma_bf16(oacc[nf], ph, bv[nf]);    // ph*vh
                #pragma unroll
                for (int nf = 0; nf < 8; nf++)
                    mma_bf16(oacc[nf], pl, bv[nf]);    // pl*vh
                #pragma unroll
                for (int nf2 = 0; nf2 < 4; nf2++) {
                    uint32_t t4[4];
                    ldsm_x4(t4, base + 3 * FK_BYTES +
                            (uint32_t)(nf2 * 16) * ROW2 + kf * 32 + bRowCol);
                    bv[nf2*2][0] = t4[0]; bv[nf2*2][1] = t4[1];
                    bv[nf2*2+1][0] = t4[2]; bv[nf2*2+1][1] = t4[3];
                }
                #pragma unroll
                for (int nf = 0; nf < 8; nf++)
                    mma_bf16(oacc[nf], ph, bv[nf]);    // ph*vl
            }
        }

        __syncthreads();
        if (t + 2 < nt) issueKV(t + 2, st);
    }

    const float inv0 = 1.f / l0;
    const float inv1 = 1.f / l1;
    const int b = bh >> 4;
    const int h = bh & 15;
    const int row0 = qb + w * 16 + lr;
    const int row1 = row0 + 8;
    #pragma unroll
    for (int nf = 0; nf < 8; nf++) {
        const int col = h * 64 + nf * 8 + lc;
        const float v0 = oacc[nf][0] * inv0, v1 = oacc[nf][1] * inv0;
        const float v2 = oacc[nf][2] * inv1, v3 = oacc[nf][3] * inv1;
        __nv_bfloat16 h0, h1, h2, h3, e0, e1, e2, e3;
        split_bf(v0, h0, e0); split_bf(v1, h1, e1);
        split_bf(v2, h2, e2); split_bf(v3, h3, e3);
        const size_t i0 = ((size_t)(b * SEQ + row0)) * DMODEL + col;
        const size_t i1 = ((size_t)(b * SEQ + row1)) * DMODEL + col;
        *(uint32_t*)&g_attn_hi[i0] = pack_bf2(h0, h1);
        *(uint32_t*)&g_attn_lo[i0] = pack_bf2(e0, e1);
        *(uint32_t*)&g_attn_hi[i1] = pack_bf2(h2, h3);
        *(uint32_t*)&g_attn_lo[i1] = pack_bf2(e2, e3);
    }
}

// ---------------------------------------------------------------------------
extern "C" void kernel_launch(void* const* d_in, const int* in_sizes, int n_in,
                              void* d_out, int out_size)
{
    (void)in_sizes; (void)n_in; (void)out_size;
    const float* x    = (const float*)d_in[0];
    const float* Wqkv = (const float*)d_in[1];
    const float* bqkv = (const float*)d_in[2];
    const float* Wout = (const float*)d_in[3];
    const float* bout = (const float*)d_in[4];
    float* out = (float*)d_out;

    __nv_bfloat16 *xh, *xl, *wqh, *wql, *woh, *wol, *ah, *al;
    cudaGetSymbolAddress((void**)&xh,  g_x_hi);
    cudaGetSymbolAddress((void**)&xl,  g_x_lo);
    cudaGetSymbolAddress((void**)&wqh, g_wq_hi);
    cudaGetSymbolAddress((void**)&wql, g_wq_lo);
    cudaGetSymbolAddress((void**)&woh, g_wo_hi);
    cudaGetSymbolAddress((void**)&wol, g_wo_lo);
    cudaGetSymbolAddress((void**)&ah,  g_attn_hi);
    cudaGetSymbolAddress((void**)&al,  g_attn_lo);

    cudaFuncSetAttribute(mma_gemm<0>, cudaFuncAttributeMaxDynamicSharedMemorySize, SMEM_GEMM);
    cudaFuncSetAttribute(mma_gemm<1>, cudaFuncAttributeMaxDynamicSharedMemorySize, SMEM_GEMM);
    cudaFuncSetAttribute(flash_mma, cudaFuncAttributeMaxDynamicSharedMemorySize, SMEM_FLASH);

    conv_split<<<(MROWS * KDIM) / (256 * 4), 256>>>(x, xh, xl);
    transpose_split<<<dim3(NQKV / 32, KDIM / 32), dim3(32, 8)>>>(Wqkv, wqh, wql, KDIM, NQKV);
    transpose_split<<<dim3(DMODEL / 32, KDIM / 32), dim3(32, 8)>>>(Wout, woh, wol, KDIM, DMODEL);

    // QKV projection -> Q/K bf16 hi/lo + V fp32
    mma_gemm<0><<<dim3(NQKV / 128, MROWS / 128), 128, SMEM_GEMM>>>(
        xh, xl, wqh, wql, bqkv, nullptr);

    // V transpose + split
    vtrans_kernel<<<dim3(DH / 32, SEQ / 32, NBH), dim3(32, 8)>>>();

    // tensor-core causal flash attention -> attn hi/lo
    flash_mma<<<dim3(SEQ / 128, NBH), 256, SMEM_FLASH>>>();

    // output projection -> d_out
    mma_gemm<1><<<dim3(DMODEL / 128, MROWS / 128), 128, SMEM_FLASH ? SMEM_GEMM : SMEM_GEMM>>>(
        ah, al, woh, wol, bout, out);
}

// round 7
// speedup vs baseline: 1.6094x; 1.6094x over previous
#include <cuda_runtime.h>
#include <cuda_bf16.h>
#include <cstdint>

#define BATCH 2
#define SEQ 2048
#define HEADS 16
#define DH 64
#define DMODEL 1024
#define MROWS (BATCH*SEQ)   // 4096
#define KDIM 1024
#define NQKV 3072
#define NBH (BATCH*HEADS)   // 32

// ---------------- device scratch (allocation-free rule) ----------------
__device__ __nv_bfloat16 g_Qh[NBH*SEQ*DH];
__device__ __nv_bfloat16 g_Ql[NBH*SEQ*DH];
__device__ __nv_bfloat16 g_Kh[NBH*SEQ*DH];
__device__ __nv_bfloat16 g_Kl[NBH*SEQ*DH];
__device__ float         g_V [NBH*SEQ*DH];
__device__ __nv_bfloat16 g_Vth[NBH*DH*SEQ];   // V^T [bh][d][s]
__device__ __nv_bfloat16 g_Vtl[NBH*DH*SEQ];
__device__ __nv_bfloat16 g_x_hi[MROWS*KDIM];
__device__ __nv_bfloat16 g_x_lo[MROWS*KDIM];
__device__ __nv_bfloat16 g_wq_hi[NQKV*KDIM];   // Wqkv^T [N,K]
__device__ __nv_bfloat16 g_wq_lo[NQKV*KDIM];
__device__ __nv_bfloat16 g_wo_hi[DMODEL*KDIM]; // Wout^T [N,K]
__device__ __nv_bfloat16 g_wo_lo[DMODEL*KDIM];
__device__ __nv_bfloat16 g_attn_hi[MROWS*DMODEL];
__device__ __nv_bfloat16 g_attn_lo[MROWS*DMODEL];

// ---------------- helpers ----------------
__device__ __forceinline__ uint32_t smem_u32(const void* p) {
    uint32_t a;
    asm("{ .reg .u64 t; cvta.to.shared.u64 t, %1; cvt.u32.u64 %0, t; }" : "=r"(a) : "l"(p));
    return a;
}
__device__ __forceinline__ void cpa16(uint32_t dst, const void* src) {
    asm volatile("cp.async.cg.shared.global [%0], [%1], 16;" :: "r"(dst), "l"(src) : "memory");
}
__device__ __forceinline__ void cpa_commit() {
    asm volatile("cp.async.commit_group;" ::: "memory");
}
__device__ __forceinline__ void ldsm_x4(uint32_t* r, uint32_t addr) {
    asm volatile("ldmatrix.sync.aligned.m8n8.x4.shared.b16 {%0,%1,%2,%3}, [%4];"
        : "=r"(r[0]), "=r"(r[1]), "=r"(r[2]), "=r"(r[3]) : "r"(addr));
}
__device__ __forceinline__ void mma_bf16(float* c, const uint32_t* a, const uint32_t* b) {
    asm volatile(
        "mma.sync.aligned.m16n8k16.row.col.f32.bf16.bf16.f32 "
        "{%0,%1,%2,%3}, {%4,%5,%6,%7}, {%8,%9}, {%0,%1,%2,%3};"
        : "+f"(c[0]), "+f"(c[1]), "+f"(c[2]), "+f"(c[3])
        : "r"(a[0]), "r"(a[1]), "r"(a[2]), "r"(a[3]), "r"(b[0]), "r"(b[1]));
}
__device__ __forceinline__ uint32_t pack_bf2(__nv_bfloat16 a, __nv_bfloat16 b) {
    return (uint32_t)__bfloat16_as_ushort(a) | ((uint32_t)__bfloat16_as_ushort(b) << 16);
}
__device__ __forceinline__ void split_bf(float v, __nv_bfloat16& h, __nv_bfloat16& l) {
    h = __float2bfloat16(v);
    l = __float2bfloat16(v - __bfloat162float(h));
}

// ---------------- split-convert kernels ----------------
__global__ __launch_bounds__(256) void conv_split(const float* __restrict__ in,
                                                  __nv_bfloat16* __restrict__ hi,
                                                  __nv_bfloat16* __restrict__ lo) {
    const size_t i = (size_t)blockIdx.x * 256 + threadIdx.x;
    float4 v = ((const float4*)in)[i];
    __nv_bfloat16 h0, h1, h2, h3, l0, l1, l2, l3;
    split_bf(v.x, h0, l0); split_bf(v.y, h1, l1);
    split_bf(v.z, h2, l2); split_bf(v.w, h3, l3);
    ((uint2*)hi)[i] = make_uint2(pack_bf2(h0, h1), pack_bf2(h2, h3));
    ((uint2*)lo)[i] = make_uint2(pack_bf2(l0, l1), pack_bf2(l2, l3));
}

// W[K,N] (row-major) -> Wt_hi/lo[N,K] bf16
__global__ __launch_bounds__(256) void transpose_split(const float* __restrict__ W,
                                                       __nv_bfloat16* __restrict__ th,
                                                       __nv_bfloat16* __restrict__ tl,
                                                       int K, int N) {
    __shared__ float t[32][33];
    const int tx = threadIdx.x, ty = threadIdx.y;
    #pragma unroll
    for (int r = 0; r < 4; r++) {
        int k = blockIdx.y * 32 + ty + r * 8;
        int n = blockIdx.x * 32 + tx;
        t[ty + r * 8][tx] = W[(size_t)k * N + n];
    }
    __syncthreads();
    #pragma unroll
    for (int r = 0; r < 4; r++) {
        int n = blockIdx.x * 32 + ty + r * 8;
        int k = blockIdx.y * 32 + tx;
        float v = t[tx][ty + r * 8];
        __nv_bfloat16 h, l;
        split_bf(v, h, l);
        th[(size_t)n * K + k] = h;
        tl[(size_t)n * K + k] = l;
    }
}

// V [bh][s][d] fp32 -> Vt hi/lo [bh][d][s] bf16
__global__ __launch_bounds__(256) void vtrans_kernel() {
    __shared__ float t[32][33];
    const int tx = threadIdx.x, ty = threadIdx.y;
    const int d0 = blockIdx.x * 32, s0 = blockIdx.y * 32, bh = blockIdx.z;
    #pragma unroll
    for (int r = 0; r < 4; r++) {
        int s = s0 + ty + r * 8;
        t[ty + r * 8][tx] = g_V[((size_t)bh * SEQ + s) * DH + d0 + tx];
    }
    __syncthreads();
    #pragma unroll
    for (int r = 0; r < 4; r++) {
        int d = d0 + ty + r * 8;
        int s = s0 + tx;
        float v = t[tx][ty + r * 8];
        __nv_bfloat16 h, l;
        split_bf(v, h, l);
        g_Vth[((size_t)bh * DH + d) * SEQ + s] = h;
        g_Vtl[((size_t)bh * DH + d) * SEQ + s] = l;
    }
}

// ---------------- mma.sync bf16x3 GEMM (round-4 proven version) ----------------
// 128x128 tile, 8 warps (2x4), warp tile 64x32, K chunks of 32, cp.async double buffer.
#define BK 32
#define ROWB 80
#define MATB (128*ROWB)
#define OFF_AH 0
#define OFF_AL MATB
#define OFF_BH (2*MATB)
#define OFF_BL (3*MATB)
#define STAGEB (4*MATB)
#define NCH (KDIM/BK)
#define SMEM_GEMM (2*STAGEB)

template<int EPI>
__global__ __launch_bounds__(256)
void mma_gemm(const __nv_bfloat16* __restrict__ Ah, const __nv_bfloat16* __restrict__ Al,
              const __nv_bfloat16* __restrict__ Bh, const __nv_bfloat16* __restrict__ Bl,
              const float* __restrict__ bias, float* __restrict__ Cout)
{
    extern __shared__ char smem[];
    const uint32_t sb = smem_u32(smem);
    const int tid = threadIdx.x;
    const int lane = tid & 31;
    const int wid = tid >> 5;
    const int rowBase = blockIdx.y * 128;
    const int colBase = blockIdx.x * 128;
    const int mBase = (wid & 1) * 64;
    const int nBase = (wid >> 1) * 32;

    int rI[2], qI[2];
    #pragma unroll
    for (int j = 0; j < 2; j++) {
        int u = tid + j * 256;
        rI[j] = u >> 2;
        qI[j] = u & 3;
    }

    auto issue = [&](int c, int st) {
        const int k0 = c * BK;
        const uint32_t base = sb + st * STAGEB;
        #pragma unroll
        for (int j = 0; j < 2; j++) {
            const uint32_t so = (uint32_t)(rI[j] * ROWB + qI[j] * 16);
            const size_t offA = (size_t)(rowBase + rI[j]) * KDIM + k0 + qI[j] * 8;
            const size_t offB = (size_t)(colBase + rI[j]) * KDIM + k0 + qI[j] * 8;
            cpa16(base + OFF_AH + so, Ah + offA);
            cpa16(base + OFF_AL + so, Al + offA);
            cpa16(base + OFF_BH + so, Bh + offB);
            cpa16(base + OFF_BL + so, Bl + offB);
        }
        cpa_commit();
    };

    float acc[4][4][4];
    #pragma unroll
    for (int i = 0; i < 4; i++)
        #pragma unroll
        for (int j = 0; j < 4; j++)
            #pragma unroll
            for (int r = 0; r < 4; r++) acc[i][j][r] = 0.f;

    issue(0, 0);
    issue(1, 1);

    const int ja = lane >> 3;
    const int ra = lane & 7;
    const uint32_t aRowCol = (uint32_t)(((ja & 1) * 8 + ra) * ROWB + (ja >> 1) * 16);
    const uint32_t bRowCol = (uint32_t)((((lane >> 4) * 8) + ra) * ROWB + ((lane >> 3) & 1) * 16);

    for (int c = 0; c < NCH; c++) {
        if (c == NCH - 1)
            asm volatile("cp.async.wait_group 0;" ::: "memory");
        else
            asm volatile("cp.async.wait_group 1;" ::: "memory");
        __syncthreads();

        const int st = c & 1;
        const uint32_t base = sb + st * STAGEB;

        #pragma unroll
        for (int kb = 0; kb < 2; kb++) {
            uint32_t ah[4][4], al[4][4];
            #pragma unroll
            for (int mf = 0; mf < 4; mf++) {
                const uint32_t off = (uint32_t)((mBase + mf * 16) * ROWB + kb * 32) + aRowCol;
                ldsm_x4(ah[mf], base + OFF_AH + off);
                ldsm_x4(al[mf], base + OFF_AL + off);
            }
            uint32_t bh[4][2], bl[4][2];
            #pragma unroll
            for (int nf2 = 0; nf2 < 2; nf2++) {
                const uint32_t off = (uint32_t)((nBase + nf2 * 16) * ROWB + kb * 32) + bRowCol;
                uint32_t t4[4];
                ldsm_x4(t4, base + OFF_BH + off);
                bh[nf2*2][0] = t4[0]; bh[nf2*2][1] = t4[1];
                bh[nf2*2+1][0] = t4[2]; bh[nf2*2+1][1] = t4[3];
                ldsm_x4(t4, base + OFF_BL + off);
                bl[nf2*2][0] = t4[0]; bl[nf2*2][1] = t4[1];
                bl[nf2*2+1][0] = t4[2]; bl[nf2*2+1][1] = t4[3];
            }
            #pragma unroll
            for (int mf = 0; mf < 4; mf++)
                #pragma unroll
                for (int nf = 0; nf < 4; nf++) {
                    mma_bf16(acc[mf][nf], ah[mf], bh[nf]);
                    mma_bf16(acc[mf][nf], ah[mf], bl[nf]);
                    mma_bf16(acc[mf][nf], al[mf], bh[nf]);
                }
        }
        __syncthreads();
        if (c + 2 < NCH) issue(c + 2, st);
    }

    // epilogue
    #pragma unroll
    for (int mf = 0; mf < 4; mf++) {
        #pragma unroll
        for (int rp = 0; rp < 2; rp++) {
            const int m = rowBase + mBase + mf * 16 + (lane >> 2) + rp * 8;
            const int b = m >> 11;
            const int s_ = m & (SEQ - 1);
            #pragma unroll
            for (int nf = 0; nf < 4; nf++) {
                const int n0 = colBase + nBase + nf * 8 + (lane & 3) * 2;
                const float v0 = acc[mf][nf][rp * 2 + 0] + bias[n0];
                const float v1 = acc[mf][nf][rp * 2 + 1] + bias[n0 + 1];
                if (EPI == 0) {
                    const int h = n0 / 192;
                    const int rr = n0 - h * 192;
                    const size_t bhBase = (size_t)(b * HEADS + h) * SEQ + s_;
                    __nv_bfloat16 h0, h1, l0, l1;
                    split_bf(v0, h0, l0);
                    split_bf(v1, h1, l1);
                    if (rr < 64) {
                        const size_t idx = bhBase * DH + rr;
                        *(uint32_t*)&g_Qh[idx] = pack_bf2(h0, h1);
                        *(uint32_t*)&g_Ql[idx] = pack_bf2(l0, l1);
                    } else if (rr < 128) {
                        const size_t idx = bhBase * DH + (rr - 64);
                        *(uint32_t*)&g_Kh[idx] = pack_bf2(h0, h1);
                        *(uint32_t*)&g_Kl[idx] = pack_bf2(l0, l1);
                    } else {
                        const size_t idx = bhBase * DH + (rr - 128);
                        *(float2*)&g_V[idx] = make_float2(v0, v1);
                    }
                } else {
                    *(float2*)&Cout[(size_t)m * DMODEL + n0] = make_float2(v0, v1);
                }
            }
        }
    }
}

// ---------------- tensor-core flash attention (round-4 order + causal pairing) ----------------
// Each CTA handles TWO q-tiles: qt = bx and qt = 15-bx -> uniform 17 units of work.
#define ROW2 144
#define FQ_BYTES (128*ROW2)
#define FK_BYTES (64*ROW2)
#define FO_QH 0
#define FO_QL FQ_BYTES
#define FO_STAGE (2*FQ_BYTES)
#define FSTAGEB (4*FK_BYTES)
#define SMEM_FLASH (FO_STAGE + 2*FSTAGEB)
#define NQT (SEQ/128)          // 16

__global__ __launch_bounds__(256, 2)
void flash_mma()
{
    extern __shared__ char smem[];
    const uint32_t sb = smem_u32(smem);
    const int tid = threadIdx.x;
    const int lane = tid & 31;
    const int w = tid >> 5;
    const int bx = blockIdx.x;       // 0..7
    const int bh = blockIdx.y;

    const int lr = lane >> 2;
    const int lc = (lane & 3) * 2;

    const __nv_bfloat16* Qh = g_Qh + (size_t)bh * SEQ * DH;
    const __nv_bfloat16* Ql = g_Ql + (size_t)bh * SEQ * DH;
    const __nv_bfloat16* Kh = g_Kh + (size_t)bh * SEQ * DH;
    const __nv_bfloat16* Kl = g_Kl + (size_t)bh * SEQ * DH;
    const __nv_bfloat16* Vth = g_Vth + (size_t)bh * DH * SEQ;
    const __nv_bfloat16* Vtl = g_Vtl + (size_t)bh * DH * SEQ;

    const int ja = lane >> 3;
    const int ra = lane & 7;
    const uint32_t aRowCol = (uint32_t)(((ja & 1) * 8 + ra) * ROW2 + (ja >> 1) * 16);
    const uint32_t bRowCol = (uint32_t)((((lane >> 4) * 8) + ra) * ROW2 + ((lane >> 3) & 1) * 16);
    const uint32_t qWarpOff = (uint32_t)(w * 16) * ROW2 + aRowCol;

    auto issueKV = [&](int t, int st) {
        const int kv0 = t * 64;
        const uint32_t base = sb + FO_STAGE + st * FSTAGEB;
        #pragma unroll
        for (int j = 0; j < 2; j++) {
            const int u = tid + j * 256;
            const int r = u >> 3, c = u & 7;
            const uint32_t so = (uint32_t)(r * ROW2 + c * 16);
            const size_t offK = (size_t)(kv0 + r) * DH + c * 8;
            const size_t offV = (size_t)r * SEQ + kv0 + c * 8;
            cpa16(base + 0 * FK_BYTES + so, Kh + offK);
            cpa16(base + 1 * FK_BYTES + so, Kl + offK);
            cpa16(base + 2 * FK_BYTES + so, Vth + offV);
            cpa16(base + 3 * FK_BYTES + so, Vtl + offV);
        }
        cpa_commit();
    };

    #pragma unroll 1
    for (int rep = 0; rep < 2; rep++) {
        const int qt = (rep == 0) ? bx : (NQT - 1 - bx);
        const int qb = qt * 128;
        const int nt = 2 * qt + 2;

        // Q load (joins issueKV(0,0)'s commit group)
        #pragma unroll
        for (int j = 0; j < 4; j++) {
            const int u = tid + j * 256;
            const int r = u >> 3, c = u & 7;
            const uint32_t so = (uint32_t)(r * ROW2 + c * 16);
            const size_t off = (size_t)(qb + r) * DH + c * 8;
            cpa16(sb + FO_QH + so, Qh + off);
            cpa16(sb + FO_QL + so, Ql + off);
        }
        issueKV(0, 0);
        issueKV(1, 1);

        float oacc[8][4];
        #pragma unroll
        for (int nf = 0; nf < 8; nf++)
            #pragma unroll
            for (int r = 0; r < 4; r++) oacc[nf][r] = 0.f;
        float m0 = -1e30f, m1 = -1e30f, l0 = 0.f, l1 = 0.f;

        const int qrow_last = qb + w * 16 + 15;

        for (int t = 0; t < nt; t++) {
            if (t == nt - 1)
                asm volatile("cp.async.wait_group 0;" ::: "memory");
            else
                asm volatile("cp.async.wait_group 1;" ::: "memory");
            __syncthreads();

            const int kv0 = t * 64;
            const int st = t & 1;
            const uint32_t base = sb + FO_STAGE + st * FSTAGEB;

            if (kv0 <= qrow_last) {
                float sacc[8][4];
                #pragma unroll
                for (int nf = 0; nf < 8; nf++)
                    #pragma unroll
                    for (int r = 0; r < 4; r++) sacc[nf][r] = 0.f;

                #pragma unroll
                for (int kf = 0; kf < 4; kf++) {
                    uint32_t qh4[4], ql4[4];
                    ldsm_x4(qh4, sb + FO_QH + qWarpOff + kf * 32);
                    ldsm_x4(ql4, sb + FO_QL + qWarpOff + kf * 32);
                    uint32_t bb[8][2];
                    #pragma unroll
                    for (int nf2 = 0; nf2 < 4; nf2++) {
                        uint32_t t4[4];
                        ldsm_x4(t4, base + 0 * FK_BYTES +
                                (uint32_t)(nf2 * 16) * ROW2 + kf * 32 + bRowCol);
                        bb[nf2*2][0] = t4[0]; bb[nf2*2][1] = t4[1];
                        bb[nf2*2+1][0] = t4[2]; bb[nf2*2+1][1] = t4[3];
                    }
                    #pragma unroll
                    for (int nf = 0; nf < 8; nf++) {
                        mma_bf16(sacc[nf], qh4, bb[nf]);
                        mma_bf16(sacc[nf], ql4, bb[nf]);
                    }
                    #pragma unroll
                    for (int nf2 = 0; nf2 < 4; nf2++) {
                        uint32_t t4[4];
                        ldsm_x4(t4, base + 1 * FK_BYTES +
                                (uint32_t)(nf2 * 16) * ROW2 + kf * 32 + bRowCol);
                        bb[nf2*2][0] = t4[0]; bb[nf2*2][1] = t4[1];
                        bb[nf2*2+1][0] = t4[2]; bb[nf2*2+1][1] = t4[3];
                    }
                    #pragma unroll
                    for (int nf = 0; nf < 8; nf++)
                        mma_bf16(sacc[nf], qh4, bb[nf]);
                }

                const bool needMask = (kv0 + 63) > (qb + w * 16);
                const int row0 = qb + w * 16 + lr;
                const int row1 = row0 + 8;
                #pragma unroll
                for (int nf = 0; nf < 8; nf++) {
                    const int c0 = kv0 + nf * 8 + lc;
                    #pragma unroll
                    for (int r = 0; r < 4; r++) {
                        float v = sacc[nf][r] * 0.125f;
                        if (needMask) {
                            const int col = c0 + (r & 1);
                            const int row = (r < 2) ? row0 : row1;
                            if (col > row) v = -1e30f;
                        }
                        sacc[nf][r] = v;
                    }
                }

                float mx0 = -1e30f, mx1 = -1e30f;
                #pragma unroll
                for (int nf = 0; nf < 8; nf++) {
                    mx0 = fmaxf(mx0, fmaxf(sacc[nf][0], sacc[nf][1]));
                    mx1 = fmaxf(mx1, fmaxf(sacc[nf][2], sacc[nf][3]));
                }
                mx0 = fmaxf(mx0, __shfl_xor_sync(0xffffffffu, mx0, 1));
                mx0 = fmaxf(mx0, __shfl_xor_sync(0xffffffffu, mx0, 2));
                mx1 = fmaxf(mx1, __shfl_xor_sync(0xffffffffu, mx1, 1));
                mx1 = fmaxf(mx1, __shfl_xor_sync(0xffffffffu, mx1, 2));
                const float nm0 = fmaxf(m0, mx0);
                const float nm1 = fmaxf(m1, mx1);
                const float corr0 = __expf(m0 - nm0);
                const float corr1 = __expf(m1 - nm1);
                m0 = nm0; m1 = nm1;

                float rs0 = 0.f, rs1 = 0.f;
                #pragma unroll
                for (int nf = 0; nf < 8; nf++) {
                    float p0 = __expf(sacc[nf][0] - m0);
                    float p1 = __expf(sacc[nf][1] - m0);
                    float p2 = __expf(sacc[nf][2] - m1);
                    float p3 = __expf(sacc[nf][3] - m1);
                    sacc[nf][0] = p0; sacc[nf][1] = p1;
                    sacc[nf][2] = p2; sacc[nf][3] = p3;
                    rs0 += p0 + p1; rs1 += p2 + p3;
                }
                rs0 += __shfl_xor_sync(0xffffffffu, rs0, 1);
                rs0 += __shfl_xor_sync(0xffffffffu, rs0, 2);
                rs1 += __shfl_xor_sync(0xffffffffu, rs1, 1);
                rs1 += __shfl_xor_sync(0xffffffffu, rs1, 2);
                l0 = l0 * corr0 + rs0;
                l1 = l1 * corr1 + rs1;

                #pragma unroll
                for (int nf = 0; nf < 8; nf++) {
                    oacc[nf][0] *= corr0; oacc[nf][1] *= corr0;
                    oacc[nf][2] *= corr1; oacc[nf][3] *= corr1;
                }

                #pragma unroll
                for (int kf = 0; kf < 4; kf++) {
                    __nv_bfloat16 h0, h1, h2, h3, e0, e1, e2, e3;
                    uint32_t ph[4], pl[4];
                    split_bf(sacc[2*kf][0], h0, e0); split_bf(sacc[2*kf][1], h1, e1);
                    split_bf(sacc[2*kf][2], h2, e2); split_bf(sacc[2*kf][3], h3, e3);
                    ph[0] = pack_bf2(h0, h1); ph[1] = pack_bf2(h2, h3);
                    pl[0] = pack_bf2(e0, e1); pl[1] = pack_bf2(e2, e3);
                    split_bf(sacc[2*kf+1][0], h0, e0); split_bf(sacc[2*kf+1][1], h1, e1);
                    split_bf(sacc[2*kf+1][2], h2, e2); split_bf(sacc[2*kf+1][3], h3, e3);
                    ph[2] = pack_bf2(h0, h1); ph[3] = pack_bf2(h2, h3);
                    pl[2] = pack_bf2(e0, e1); pl[3] = pack_bf2(e2, e3);

                    uint32_t bv[8][2];
                    #pragma unroll
                    for (int nf2 = 0; nf2 < 4; nf2++) {
                        uint32_t t4[4];
                        ldsm_x4(t4, base + 2 * FK_BYTES +
                                (uint32_t)(nf2 * 16) * ROW2 + kf * 32 + bRowCol);
                        bv[nf2*2][0] = t4[0]; bv[nf2*2][1] = t4[1];
                        bv[nf2*2+1][0] = t4[2]; bv[nf2*2+1][1] = t4[3];
                    }
                    #pragma unroll
                    for (int nf = 0; nf < 8; nf++) {
                        mma_bf16(oacc[nf], ph, bv[nf]);
                        mma_bf16(oacc[nf], pl, bv[nf]);
                    }
                    #pragma unroll
                    for (int nf2 = 0; nf2 < 4; nf2++) {
                        uint32_t t4[4];
                        ldsm_x4(t4, base + 3 * FK_BYTES +
                                (uint32_t)(nf2 * 16) * ROW2 + kf * 32 + bRowCol);
                        bv[nf2*2][0] = t4[0]; bv[nf2*2][1] = t4[1];
                        bv[nf2*2+1][0] = t4[2]; bv[nf2*2+1][1] = t4[3];
                    }
                    #pragma unroll
                    for (int nf = 0; nf < 8; nf++)
                        mma_bf16(oacc[nf], ph, bv[nf]);
                }
            }

            __syncthreads();
            if (t + 2 < nt) issueKV(t + 2, st);
        }

        // normalize + write attn hi/lo for this q-tile
        const float inv0 = 1.f / l0;
        const float inv1 = 1.f / l1;
        const int b = bh >> 4;
        const int h = bh & 15;
        const int row0 = qb + w * 16 + lr;
        const int row1 = row0 + 8;
        #pragma unroll
        for (int nf = 0; nf < 8; nf++) {
            const int col = h * 64 + nf * 8 + lc;
            const float v0 = oacc[nf][0] * inv0, v1 = oacc[nf][1] * inv0;
            const float v2 = oacc[nf][2] * inv1, v3 = oacc[nf][3] * inv1;
            __nv_bfloat16 h0, h1, h2, h3, e0, e1, e2, e3;
            split_bf(v0, h0, e0); split_bf(v1, h1, e1);
            split_bf(v2, h2, e2); split_bf(v3, h3, e3);
            const size_t i0 = ((size_t)(b * SEQ + row0)) * DMODEL + col;
            const size_t i1 = ((size_t)(b * SEQ + row1)) * DMODEL + col;
            *(uint32_t*)&g_attn_hi[i0] = pack_bf2(h0, h1);
            *(uint32_t*)&g_attn_lo[i0] = pack_bf2(e0, e1);
            *(uint32_t*)&g_attn_hi[i1] = pack_bf2(h2, h3);
            *(uint32_t*)&g_attn_lo[i1] = pack_bf2(e2, e3);
        }
        __syncthreads();   // all smem reads done before next rep's Q overwrite
    }
}

// ---------------------------------------------------------------------------
extern "C" void kernel_launch(void* const* d_in, const int* in_sizes, int n_in,
                              void* d_out, int out_size)
{
    (void)in_sizes; (void)n_in; (void)out_size;
    const float* x    = (const float*)d_in[0];
    const float* Wqkv = (const float*)d_in[1];
    const float* bqkv = (const float*)d_in[2];
    const float* Wout = (const float*)d_in[3];
    const float* bout = (const float*)d_in[4];
    float* out = (float*)d_out;

    __nv_bfloat16 *xh, *xl, *wqh, *wql, *woh, *wol, *ah, *al;
    cudaGetSymbolAddress((void**)&xh,  g_x_hi);
    cudaGetSymbolAddress((void**)&xl,  g_x_lo);
    cudaGetSymbolAddress((void**)&wqh, g_wq_hi);
    cudaGetSymbolAddress((void**)&wql, g_wq_lo);
    cudaGetSymbolAddress((void**)&woh, g_wo_hi);
    cudaGetSymbolAddress((void**)&wol, g_wo_lo);
    cudaGetSymbolAddress((void**)&ah,  g_attn_hi);
    cudaGetSymbolAddress((void**)&al,  g_attn_lo);

    cudaFuncSetAttribute(mma_gemm<0>, cudaFuncAttributeMaxDynamicSharedMemorySize, SMEM_GEMM);
    cudaFuncSetAttribute(mma_gemm<1>, cudaFuncAttributeMaxDynamicSharedMemorySize, SMEM_GEMM);
    cudaFuncSetAttribute(flash_mma, cudaFuncAttributeMaxDynamicSharedMemorySize, SMEM_FLASH);

    conv_split<<<(MROWS * KDIM) / (256 * 4), 256>>>(x, xh, xl);
    transpose_split<<<dim3(NQKV / 32, KDIM / 32), dim3(32, 8)>>>(Wqkv, wqh, wql, KDIM, NQKV);
    transpose_split<<<dim3(DMODEL / 32, KDIM / 32), dim3(32, 8)>>>(Wout, woh, wol, KDIM, DMODEL);

    // QKV projection -> Q/K bf16 hi/lo + V fp32
    mma_gemm<0><<<dim3(NQKV / 128, MROWS / 128), 256, SMEM_GEMM>>>(
        xh, xl, wqh, wql, bqkv, nullptr);

    // V transpose + split
    vtrans_kernel<<<dim3(DH / 32, SEQ / 32, NBH), dim3(32, 8)>>>();

    // tensor-core causal flash attention, pairing-balanced: grid (8, 32)
    flash_mma<<<dim3(NQT / 2, NBH), 256, SMEM_FLASH>>>();

    // output projection -> d_out
    mma_gemm<1><<<dim3(DMODEL / 128, MROWS / 128), 256, SMEM_GEMM>>>(
        ah, al, woh, wol, bout, out);
}